// round 5
// baseline (speedup 1.0000x reference)
#include <cuda_runtime.h>
#include <math.h>
#include <stdint.h>

// Problem constants
#define BB 32
#define TT 1024
#define HH 1024
#define LL 4

// Recurrence kernel config: 128 CTAs = 4 batch-groups x 32 col-groups
#define NCTA  128
#define CGRP  32        // col-groups
#define BGRP  4         // batch-groups
#define CPC   (HH/CGRP) // 32 cols per CTA
#define BPC   (BB/BGRP) // 8 batches per CTA
#define WPAD  1028      // padded SMEM row stride (floats): 4112B == 16B mod 128B -> conflict-free
#define RNN_SMEM ((CPC*WPAD + BPC*WPAD) * 4 + 64)   // 128.5KB Wh + 32.1KB h  ~= 164.5 KB

// -------------------- device scratch --------------------
__device__ float g_S0[BB * TT * HH];   // 128 MB ping
__device__ float g_S1[BB * TT * HH];   // 128 MB pong
__device__ float g_hA[BB * HH];        // h ping  (natural layout [b][k])
__device__ float g_hB[BB * HH];        // h pong
__device__ unsigned g_bar;             // grid barrier counter (reset by gemm block 0)

// Accurate tanh independent of fast-math tanhf->MUFU.TANH. ~1e-7 rel error.
__device__ __forceinline__ float tanh_acc(float x)
{
    float ax = fabsf(x);
    float e  = __expf(-2.0f * ax);
    float r  = (1.0f - e) / (1.0f + e);
    return copysignf(r, x);
}

__device__ __forceinline__ uint32_t smem_u32(const void* p)
{
    uint32_t a;
    asm("{ .reg .u64 t; cvta.to.shared.u64 t, %1; cvt.u32.u64 %0, t; }" : "=r"(a) : "l"(p));
    return a;
}
__device__ __forceinline__ void cp_async16(uint32_t dst, const void* src)
{
    asm volatile("cp.async.cg.shared.global [%0], [%1], 16;" :: "r"(dst), "l"(src));
}
__device__ __forceinline__ void cp_async_wait_all()
{
    asm volatile("cp.async.commit_group;");
    asm volatile("cp.async.wait_group 0;" ::: "memory");
}

// -------------------- GEMM: C[M,1024] = A[M,1024] @ W[1024,1024] + bias --------------------
__global__ void __launch_bounds__(256, 2)
gemm_bias_kernel(const float* __restrict__ A, const float* __restrict__ W,
                 const float* __restrict__ bias, float* __restrict__ C)
{
    if (blockIdx.x == 0 && blockIdx.y == 0 && threadIdx.x == 0) g_bar = 0u;

    __shared__ float As[8][128];
    __shared__ float Bs[8][128];

    const int tid = threadIdx.x;
    const int tx = tid & 15;
    const int ty = tid >> 4;
    const int bm = blockIdx.y;
    const int bn = blockIdx.x;

    const float* Ab = A + bm * 128 * HH;
    const float* Wb = W + bn * 128;

    float acc[8][8];
#pragma unroll
    for (int i = 0; i < 8; i++)
#pragma unroll
        for (int j = 0; j < 8; j++) acc[i][j] = 0.0f;

    const int lrow = tid >> 1;
    const int lseg = (tid & 1) * 4;
    const int bkr  = tid >> 5;
    const int bcs  = (tid & 31) * 4;

    float4 av = *(const float4*)(Ab + lrow * HH + lseg);
    float4 bv = *(const float4*)(Wb + bkr * HH + bcs);

    for (int k0 = 0; k0 < HH; k0 += 8) {
        As[lseg + 0][lrow] = av.x;
        As[lseg + 1][lrow] = av.y;
        As[lseg + 2][lrow] = av.z;
        As[lseg + 3][lrow] = av.w;
        *(float4*)&Bs[bkr][bcs] = bv;
        __syncthreads();

        if (k0 + 8 < HH) {
            av = *(const float4*)(Ab + lrow * HH + (k0 + 8) + lseg);
            bv = *(const float4*)(Wb + (k0 + 8 + bkr) * HH + bcs);
        }

#pragma unroll
        for (int kk = 0; kk < 8; kk++) {
            float a[8], b[8];
            *(float4*)&a[0] = *(const float4*)&As[kk][ty * 8];
            *(float4*)&a[4] = *(const float4*)&As[kk][ty * 8 + 4];
            *(float4*)&b[0] = *(const float4*)&Bs[kk][tx * 8];
            *(float4*)&b[4] = *(const float4*)&Bs[kk][tx * 8 + 4];
#pragma unroll
            for (int i = 0; i < 8; i++)
#pragma unroll
                for (int j = 0; j < 8; j++)
                    acc[i][j] = fmaf(a[i], b[j], acc[i][j]);
        }
        __syncthreads();
    }

#pragma unroll
    for (int i = 0; i < 8; i++) {
        const int row = bm * 128 + ty * 8 + i;
#pragma unroll
        for (int j = 0; j < 8; j += 4) {
            const int col = bn * 128 + tx * 8 + j;
            float4 o;
            o.x = acc[i][j + 0] + bias[col + 0];
            o.y = acc[i][j + 1] + bias[col + 1];
            o.z = acc[i][j + 2] + bias[col + 2];
            o.w = acc[i][j + 3] + bias[col + 3];
            *(float4*)(C + row * HH + col) = o;
        }
    }
}

// -------------------- grid barrier (monotonic counter) --------------------
__device__ __forceinline__ void grid_bar_sync(unsigned target)
{
    __syncthreads();
    if (threadIdx.x == 0) {
        __threadfence();                 // release
        atomicAdd(&g_bar, 1u);
        while (*((volatile unsigned*)&g_bar) < target) { }
        __threadfence();                 // acquire
    }
    __syncthreads();
}

// -------------------- Recurrence: one persistent kernel per layer --------------------
// CTA (gb, gc): batches [gb*8, gb*8+8), cols [gc*32, gc*32+32).
// Wh slice [32 cols][1024 k] (transposed, padded rows) resident in SMEM per layer.
// Per step: h for this CTA's 8 batches (32KB) copied via cp.async; each of the
// 256 threads computes one (b, c) output over the full k=1024 dot with
// conflict-free LDS.128 and 4 accumulator chains.
__global__ void __launch_bounds__(256, 1)
rnn_layer_kernel(float* __restrict__ xp, const float* __restrict__ Wh)
{
    extern __shared__ float sm[];
    float* Wh_s = sm;                       // [CPC][WPAD]
    float* h_s  = sm + CPC * WPAD;          // [BPC][WPAD]

    const int tid = threadIdx.x;
    const int gb  = blockIdx.x >> 5;        // 0..3 batch group
    const int gc  = blockIdx.x & 31;        // 0..31 col group
    const int b0  = gb * BPC;
    const int c0  = gc * CPC;

    // load Wh slice (transposed) once per layer
    for (int i = tid; i < CPC * HH; i += 256) {
        int c = i & (CPC - 1);
        int k = i >> 5;
        Wh_s[c * WPAD + k] = Wh[k * HH + c0 + c];
    }
    // zero initial hidden state (128 CTAs x 256 threads == 32768 == BB*HH)
    g_hA[blockIdx.x * 256 + tid] = 0.0f;

    unsigned bar = 1;
    grid_bar_sync(bar * NCTA); bar++;

    // thread -> (c, b) mapping: warp covers 8 cols x 4 batches
    const int w    = tid >> 5;
    const int lane = tid & 31;
    const int cl   = (w & 3) * 8 + (lane & 7);        // local col 0..31
    const int bl   = (w >> 2) * 4 + (lane >> 3);      // local batch 0..7
    const int c    = c0 + cl;
    const int b    = b0 + bl;

    const uint32_t hsm_base = smem_u32(h_s);
    const float4* wp = (const float4*)(Wh_s + cl * WPAD);
    const float4* hp = (const float4*)(h_s + bl * WPAD);

    float* hcur = g_hA;
    float* hnxt = g_hB;

    for (int t = 0; t < TT; t++) {
        // prefetch this step's input-projection value (hides DRAM latency)
        const int xidx = (b * TT + t) * HH + c;
        const float xv = xp[xidx];

        // async copy h[b0..b0+8][0..1024] (32KB) into padded SMEM rows
        {
            const float* src = hcur + b0 * HH;
#pragma unroll
            for (int i = 0; i < 8; i++) {
                int j  = tid + (i << 8);        // float4 index 0..2047
                int hb = j >> 8;                // 0..7
                int k4 = j & 255;
                cp_async16(hsm_base + (hb * WPAD + k4 * 4) * 4,
                           src + hb * HH + k4 * 4);
            }
            cp_async_wait_all();
        }
        __syncthreads();

        // full-k dot product, 4 accumulator chains, conflict-free LDS.128
        float a0 = 0.f, a1 = 0.f, a2 = 0.f, a3 = 0.f;
#pragma unroll 8
        for (int k4 = 0; k4 < 256; k4 += 2) {
            float4 w0 = wp[k4], w1 = wp[k4 + 1];
            float4 h0 = hp[k4], h1 = hp[k4 + 1];
            a0 = fmaf(h0.x, w0.x, a0);
            a1 = fmaf(h0.y, w0.y, a1);
            a2 = fmaf(h0.z, w0.z, a2);
            a3 = fmaf(h0.w, w0.w, a3);
            a0 = fmaf(h1.x, w1.x, a0);
            a1 = fmaf(h1.y, w1.y, a1);
            a2 = fmaf(h1.z, w1.z, a2);
            a3 = fmaf(h1.w, w1.w, a3);
        }
        float hn = tanh_acc(xv + ((a0 + a1) + (a2 + a3)));

        xp[xidx]         = hn;      // in-place: xp becomes next layer's input seq
        hnxt[b * HH + c] = hn;      // h for next step

        grid_bar_sync(bar * NCTA); bar++;
        float* tmp = hcur; hcur = hnxt; hnxt = tmp;
    }
}

// -------------------- Final dense head --------------------
__global__ void __launch_bounds__(256)
fc_kernel(const float* __restrict__ seq, const float* __restrict__ fcW,
          const float* __restrict__ fcb, float* __restrict__ out)
{
    const int o = blockIdx.x * 256 + threadIdx.x;
    const int bq = blockIdx.y;
    const float* h = seq + (bq * TT + (TT - 1)) * HH;
    float acc = fcb[o];
#pragma unroll 8
    for (int k = 0; k < HH; k++)
        acc = fmaf(h[k], fcW[k * HH + o], acc);
    out[bq * HH + o] = acc;
}

// -------------------- launch --------------------
extern "C" void kernel_launch(void* const* d_in, const int* in_sizes, int n_in,
                              void* d_out, int out_size)
{
    const float* x   = (const float*)d_in[0];
    const float* Wi  = (const float*)d_in[1];
    const float* Wh  = (const float*)d_in[2];
    const float* bl  = (const float*)d_in[3];
    const float* fcW = (const float*)d_in[4];
    const float* fcb = (const float*)d_in[5];
    float* out = (float*)d_out;

    cudaFuncSetAttribute(rnn_layer_kernel,
                         cudaFuncAttributeMaxDynamicSharedMemorySize, RNN_SMEM);

    float *S0, *S1;
    cudaGetSymbolAddress((void**)&S0, g_S0);
    cudaGetSymbolAddress((void**)&S1, g_S1);

    const dim3 ggrid(8, 256);

    gemm_bias_kernel<<<ggrid, 256>>>(x,  Wi,               bl,           S0);
    rnn_layer_kernel<<<NCTA, 256, RNN_SMEM>>>(S0, Wh);
    gemm_bias_kernel<<<ggrid, 256>>>(S0, Wi + 1 * HH * HH, bl + 1 * HH,  S1);
    rnn_layer_kernel<<<NCTA, 256, RNN_SMEM>>>(S1, Wh + 1 * HH * HH);
    gemm_bias_kernel<<<ggrid, 256>>>(S1, Wi + 2 * HH * HH, bl + 2 * HH,  S0);
    rnn_layer_kernel<<<NCTA, 256, RNN_SMEM>>>(S0, Wh + 2 * HH * HH);
    gemm_bias_kernel<<<ggrid, 256>>>(S0, Wi + 3 * HH * HH, bl + 3 * HH,  S1);
    rnn_layer_kernel<<<NCTA, 256, RNN_SMEM>>>(S1, Wh + 3 * HH * HH);

    fc_kernel<<<dim3(HH / 256, BB), 256>>>(S1, fcW, fcb, out);
}

// round 6
// speedup vs baseline: 1.4040x; 1.4040x over previous
#include <cuda_runtime.h>
#include <math.h>
#include <stdint.h>

// Problem constants
#define BB 32
#define TT 1024
#define HH 1024

// Recurrence config: 128 CTAs, each owns 8 h-columns x all 32 batches.
// 8 warps split k 8-ways (128 k each); lane = batch.
#define NCTA 128
#define CPC  8          // cols per CTA
#define KPW  128        // k-range per warp
// SMEM: w_s [1024][8] (32KB) + h_s [1024][32] (128KB) + partials [8][8][32] (8KB)
#define RNN_SMEM ((HH*CPC + HH*BB + 8*CPC*BB) * 4)

// -------------------- device scratch --------------------
__device__ float g_S0[BB * TT * HH];   // 128 MB ping
__device__ float g_S1[BB * TT * HH];   // 128 MB pong
__device__ float g_hA[HH * BB];        // h ping  (k-major: h[k][b])
__device__ float g_hB[HH * BB];        // h pong
__device__ unsigned g_bar;             // grid barrier counter (reset by gemm block 0)

// Accurate tanh independent of fast-math tanhf->MUFU.TANH. ~1e-7 rel error.
__device__ __forceinline__ float tanh_acc(float x)
{
    float ax = fabsf(x);
    float e  = __expf(-2.0f * ax);
    float r  = (1.0f - e) / (1.0f + e);
    return copysignf(r, x);
}

__device__ __forceinline__ uint32_t smem_u32(const void* p)
{
    uint32_t a;
    asm("{ .reg .u64 t; cvta.to.shared.u64 t, %1; cvt.u32.u64 %0, t; }" : "=r"(a) : "l"(p));
    return a;
}
__device__ __forceinline__ void cp_async16(uint32_t dst, const void* src)
{
    asm volatile("cp.async.cg.shared.global [%0], [%1], 16;" :: "r"(dst), "l"(src));
}
__device__ __forceinline__ void cp_async_wait_own()
{
    asm volatile("cp.async.commit_group;");
    asm volatile("cp.async.wait_group 0;" ::: "memory");
}
__device__ __forceinline__ void red_release_add(unsigned* p, unsigned v)
{
    asm volatile("red.release.gpu.global.add.u32 [%0], %1;" :: "l"(p), "r"(v) : "memory");
}
__device__ __forceinline__ unsigned ld_acquire(unsigned* p)
{
    unsigned v;
    asm volatile("ld.acquire.gpu.global.u32 %0, [%1];" : "=r"(v) : "l"(p) : "memory");
    return v;
}

// -------------------- GEMM: C[M,1024] = A[M,1024] @ W[1024,1024] + bias --------------------
__global__ void __launch_bounds__(256, 2)
gemm_bias_kernel(const float* __restrict__ A, const float* __restrict__ W,
                 const float* __restrict__ bias, float* __restrict__ C)
{
    if (blockIdx.x == 0 && blockIdx.y == 0 && threadIdx.x == 0) g_bar = 0u;

    __shared__ float As[8][128];
    __shared__ float Bs[8][128];

    const int tid = threadIdx.x;
    const int tx = tid & 15;
    const int ty = tid >> 4;
    const int bm = blockIdx.y;
    const int bn = blockIdx.x;

    const float* Ab = A + bm * 128 * HH;
    const float* Wb = W + bn * 128;

    float acc[8][8];
#pragma unroll
    for (int i = 0; i < 8; i++)
#pragma unroll
        for (int j = 0; j < 8; j++) acc[i][j] = 0.0f;

    const int lrow = tid >> 1;
    const int lseg = (tid & 1) * 4;
    const int bkr  = tid >> 5;
    const int bcs  = (tid & 31) * 4;

    float4 av = *(const float4*)(Ab + lrow * HH + lseg);
    float4 bv = *(const float4*)(Wb + bkr * HH + bcs);

    for (int k0 = 0; k0 < HH; k0 += 8) {
        As[lseg + 0][lrow] = av.x;
        As[lseg + 1][lrow] = av.y;
        As[lseg + 2][lrow] = av.z;
        As[lseg + 3][lrow] = av.w;
        *(float4*)&Bs[bkr][bcs] = bv;
        __syncthreads();

        if (k0 + 8 < HH) {
            av = *(const float4*)(Ab + lrow * HH + (k0 + 8) + lseg);
            bv = *(const float4*)(Wb + (k0 + 8 + bkr) * HH + bcs);
        }

#pragma unroll
        for (int kk = 0; kk < 8; kk++) {
            float a[8], b[8];
            *(float4*)&a[0] = *(const float4*)&As[kk][ty * 8];
            *(float4*)&a[4] = *(const float4*)&As[kk][ty * 8 + 4];
            *(float4*)&b[0] = *(const float4*)&Bs[kk][tx * 8];
            *(float4*)&b[4] = *(const float4*)&Bs[kk][tx * 8 + 4];
#pragma unroll
            for (int i = 0; i < 8; i++)
#pragma unroll
                for (int j = 0; j < 8; j++)
                    acc[i][j] = fmaf(a[i], b[j], acc[i][j]);
        }
        __syncthreads();
    }

#pragma unroll
    for (int i = 0; i < 8; i++) {
        const int row = bm * 128 + ty * 8 + i;
#pragma unroll
        for (int j = 0; j < 8; j += 4) {
            const int col = bn * 128 + tx * 8 + j;
            float4 o;
            o.x = acc[i][j + 0] + bias[col + 0];
            o.y = acc[i][j + 1] + bias[col + 1];
            o.z = acc[i][j + 2] + bias[col + 2];
            o.w = acc[i][j + 3] + bias[col + 3];
            *(float4*)(C + row * HH + col) = o;
        }
    }
}

// -------------------- grid barrier: release-red + acquire poll (no L1 flush) ------------
__device__ __forceinline__ void grid_bar_sync(unsigned target)
{
    __syncthreads();
    if (threadIdx.x == 0) {
        red_release_add(&g_bar, 1u);
        while (ld_acquire(&g_bar) < target) { }
    }
    __syncthreads();
}

// -------------------- Recurrence: one persistent kernel per layer --------------------
// CTA owns cols [c0, c0+8) x all 32 batches. Warp w covers k in [w*128, w*128+128).
// Per step/warp: cp.async its own 16KB h chunk (k-major [k][b]) -> per-warp wait;
// inner loop: 1 full-wavefront LDS.32 (h, lane=b) + 2 broadcast LDS.128 (w) + 8 FMA
// per k. 8-way k-reduction through an 8KB SMEM partial buffer, then tanh + stores.
__global__ void __launch_bounds__(256, 1)
rnn_layer_kernel(float* __restrict__ xp, const float* __restrict__ Wh)
{
    extern __shared__ float sm[];
    float* w_s = sm;                         // [HH][CPC]   w_s[k*8+c] = Wh[k][c0+c]
    float* h_s = sm + HH * CPC;              // [HH][BB]    h_s[k*32+b]
    float* p_s = sm + HH * CPC + HH * BB;    // [8 warps][CPC][BB]

    const int tid  = threadIdx.x;
    const int w    = tid >> 5;
    const int lane = tid & 31;
    const int c0   = blockIdx.x * CPC;

    // load Wh slice [1024 k][8 c] once per layer (contiguous 32B per k)
    for (int i = tid; i < HH * 2; i += 256) {         // 2048 float4 moves
        int k = i >> 1, half = (i & 1) * 4;
        *(float4*)(w_s + k * CPC + half) = *(const float4*)(Wh + k * HH + c0 + half);
    }
    // zero initial hidden state (128 CTAs x 256 = 32768 floats)
    g_hA[blockIdx.x * 256 + tid] = 0.0f;

    unsigned bar = 1;
    grid_bar_sync(bar * NCTA); bar++;

    const int kbase = w * KPW;
    const uint32_t hsm = smem_u32(h_s) + kbase * BB * 4;

    // output mapping: thread tid -> (c = tid>>5, b = tid&31)
    const int oc = c0 + w;        // output col for this thread
    const int ob = lane;          // output batch

    float* hcur = g_hA;
    float* hnxt = g_hB;

    for (int t = 0; t < TT; t++) {
        // prefetch this step's input-projection value (output mapping)
        const int xidx = (ob * TT + t) * HH + oc;
        const float xv = xp[xidx];

        // warp-private h chunk copy: 16KB = 32 float4 per lane, contiguous
        {
            const float* src = hcur + kbase * BB;
#pragma unroll
            for (int j = 0; j < 32; j++)
                cp_async16(hsm + (lane + j * 32) * 16, src + (lane + j * 32) * 4);
            cp_async_wait_own();
            __syncwarp();
        }

        // accumulate 8 columns over this warp's 128 k
        float a0 = 0.f, a1 = 0.f, a2 = 0.f, a3 = 0.f;
        float a4 = 0.f, a5 = 0.f, a6 = 0.f, a7 = 0.f;
        const float*  hp = h_s + kbase * BB + lane;
        const float4* wp = (const float4*)(w_s + kbase * CPC);
#pragma unroll 4
        for (int k = 0; k < KPW; k++) {
            float  hv = hp[k * BB];          // full-wavefront LDS.32
            float4 wa = wp[k * 2];           // broadcast LDS.128
            float4 wb = wp[k * 2 + 1];       // broadcast LDS.128
            a0 = fmaf(hv, wa.x, a0);
            a1 = fmaf(hv, wa.y, a1);
            a2 = fmaf(hv, wa.z, a2);
            a3 = fmaf(hv, wa.w, a3);
            a4 = fmaf(hv, wb.x, a4);
            a5 = fmaf(hv, wb.y, a5);
            a6 = fmaf(hv, wb.z, a6);
            a7 = fmaf(hv, wb.w, a7);
        }

        // stash partials: p_s[w][c][b]
        float* pw = p_s + w * (CPC * BB) + lane;
        pw[0 * BB] = a0; pw[1 * BB] = a1; pw[2 * BB] = a2; pw[3 * BB] = a3;
        pw[4 * BB] = a4; pw[5 * BB] = a5; pw[6 * BB] = a6; pw[7 * BB] = a7;
        __syncthreads();

        // reduce 8 k-partials for output (oc, ob); conflict-free (lanes = b)
        const float* pr = p_s + w * BB + lane;   // [wslice][c=w][b=lane]
        float s = pr[0];
#pragma unroll
        for (int j = 1; j < 8; j++) s += pr[j * (CPC * BB)];

        const float hn = tanh_acc(xv + s);
        xp[xidx] = hn;                            // in-place: next layer's input
        hnxt[oc * BB + ob] = hn;                  // k-major h for next step

        grid_bar_sync(bar * NCTA); bar++;
        float* tmp = hcur; hcur = hnxt; hnxt = tmp;
    }
}

// -------------------- Final dense head --------------------
__global__ void __launch_bounds__(256)
fc_kernel(const float* __restrict__ seq, const float* __restrict__ fcW,
          const float* __restrict__ fcb, float* __restrict__ out)
{
    const int o = blockIdx.x * 256 + threadIdx.x;
    const int bq = blockIdx.y;
    const float* h = seq + (bq * TT + (TT - 1)) * HH;
    float acc = fcb[o];
#pragma unroll 8
    for (int k = 0; k < HH; k++)
        acc = fmaf(h[k], fcW[k * HH + o], acc);
    out[bq * HH + o] = acc;
}

// -------------------- launch --------------------
extern "C" void kernel_launch(void* const* d_in, const int* in_sizes, int n_in,
                              void* d_out, int out_size)
{
    const float* x   = (const float*)d_in[0];
    const float* Wi  = (const float*)d_in[1];
    const float* Wh  = (const float*)d_in[2];
    const float* bl  = (const float*)d_in[3];
    const float* fcW = (const float*)d_in[4];
    const float* fcb = (const float*)d_in[5];
    float* out = (float*)d_out;

    cudaFuncSetAttribute(rnn_layer_kernel,
                         cudaFuncAttributeMaxDynamicSharedMemorySize, RNN_SMEM);

    float *S0, *S1;
    cudaGetSymbolAddress((void**)&S0, g_S0);
    cudaGetSymbolAddress((void**)&S1, g_S1);

    const dim3 ggrid(8, 256);

    gemm_bias_kernel<<<ggrid, 256>>>(x,  Wi,               bl,           S0);
    rnn_layer_kernel<<<NCTA, 256, RNN_SMEM>>>(S0, Wh);
    gemm_bias_kernel<<<ggrid, 256>>>(S0, Wi + 1 * HH * HH, bl + 1 * HH,  S1);
    rnn_layer_kernel<<<NCTA, 256, RNN_SMEM>>>(S1, Wh + 1 * HH * HH);
    gemm_bias_kernel<<<ggrid, 256>>>(S1, Wi + 2 * HH * HH, bl + 2 * HH,  S0);
    rnn_layer_kernel<<<NCTA, 256, RNN_SMEM>>>(S0, Wh + 2 * HH * HH);
    gemm_bias_kernel<<<ggrid, 256>>>(S0, Wi + 3 * HH * HH, bl + 3 * HH,  S1);
    rnn_layer_kernel<<<NCTA, 256, RNN_SMEM>>>(S1, Wh + 3 * HH * HH);

    fc_kernel<<<dim3(HH / 256, BB), 256>>>(S1, fcW, fcb, out);
}

// round 7
// speedup vs baseline: 1.5803x; 1.1256x over previous
#include <cuda_runtime.h>
#include <cuda_bf16.h>
#include <math.h>
#include <stdint.h>

// Problem constants
#define BB 32
#define TT 1024
#define HH 1024
#define LL 4

// Recurrence config (as R6): 128 CTAs x (8 cols, all 32 batches), 8-way k-split
#define NCTA 128
#define CPC  8
#define KPW  128
#define RNN_SMEM ((HH*CPC + HH*BB + 8*CPC*BB) * 4)

// GEMM smem strides (bank-conflict-free ldmatrix)
#define AS_STRIDE 24     // 16 k-cols padded to 24 bf16 (48B rows)
#define WS_STRIDE 136    // 128 n-cols padded to 136 bf16 (272B rows)

// -------------------- device scratch --------------------
__device__ float          g_S [BB * TT * HH];    // 128 MB fp32 sequence buffer
__device__ __nv_bfloat16  g_Ah[BB * TT * HH];    // 64 MB  input hi
__device__ __nv_bfloat16  g_Al[BB * TT * HH];    // 64 MB  input lo
__device__ __nv_bfloat16  g_Wih[LL * HH * HH];   // 8 MB   Wi hi
__device__ __nv_bfloat16  g_Wil[LL * HH * HH];   // 8 MB   Wi lo
__device__ float g_hA[HH * BB];                  // h ping (k-major [k][b])
__device__ float g_hB[HH * BB];                  // h pong
__device__ unsigned g_bar;                       // grid barrier counter

// -------------------- helpers --------------------
__device__ __forceinline__ float tanh_acc(float x)
{
    float ax = fabsf(x);
    float e  = __expf(-2.0f * ax);
    float r  = (1.0f - e) / (1.0f + e);
    return copysignf(r, x);
}
__device__ __forceinline__ uint32_t smem_u32(const void* p)
{
    uint32_t a;
    asm("{ .reg .u64 t; cvta.to.shared.u64 t, %1; cvt.u32.u64 %0, t; }" : "=r"(a) : "l"(p));
    return a;
}
__device__ __forceinline__ void cp_async16(uint32_t dst, const void* src)
{
    asm volatile("cp.async.cg.shared.global [%0], [%1], 16;" :: "r"(dst), "l"(src));
}
#define CP_COMMIT() asm volatile("cp.async.commit_group;")
#define CP_WAIT(N)  asm volatile("cp.async.wait_group " #N ";" ::: "memory")

__device__ __forceinline__ void red_release_add(unsigned* p, unsigned v)
{
    asm volatile("red.release.gpu.global.add.u32 [%0], %1;" :: "l"(p), "r"(v) : "memory");
}
__device__ __forceinline__ unsigned ld_acquire(unsigned* p)
{
    unsigned v;
    asm volatile("ld.acquire.gpu.global.u32 %0, [%1];" : "=r"(v) : "l"(p) : "memory");
    return v;
}
__device__ __forceinline__ void ldsm_x4(uint32_t& r0, uint32_t& r1, uint32_t& r2, uint32_t& r3,
                                        uint32_t a)
{
    asm volatile("ldmatrix.sync.aligned.m8n8.x4.shared.b16 {%0,%1,%2,%3}, [%4];"
                 : "=r"(r0), "=r"(r1), "=r"(r2), "=r"(r3) : "r"(a));
}
__device__ __forceinline__ void ldsm_x4_t(uint32_t& r0, uint32_t& r1, uint32_t& r2, uint32_t& r3,
                                          uint32_t a)
{
    asm volatile("ldmatrix.sync.aligned.m8n8.x4.trans.shared.b16 {%0,%1,%2,%3}, [%4];"
                 : "=r"(r0), "=r"(r1), "=r"(r2), "=r"(r3) : "r"(a));
}
__device__ __forceinline__ void mma16816(float* d, uint32_t a0, uint32_t a1, uint32_t a2,
                                         uint32_t a3, uint32_t b0, uint32_t b1)
{
    asm volatile(
        "mma.sync.aligned.m16n8k16.row.col.f32.bf16.bf16.f32 "
        "{%0,%1,%2,%3}, {%4,%5,%6,%7}, {%8,%9}, {%0,%1,%2,%3};"
        : "+f"(d[0]), "+f"(d[1]), "+f"(d[2]), "+f"(d[3])
        : "r"(a0), "r"(a1), "r"(a2), "r"(a3), "r"(b0), "r"(b1));
}

// -------------------- split fp32 -> bf16 hi/lo --------------------
__global__ void __launch_bounds__(256)
split_kernel(const float* __restrict__ src, __nv_bfloat16* __restrict__ hi,
             __nv_bfloat16* __restrict__ lo, int n4)
{
    int i = blockIdx.x * blockDim.x + threadIdx.x;
    const int stride = gridDim.x * blockDim.x;
    const float4* s4 = (const float4*)src;
    __nv_bfloat162* h2 = (__nv_bfloat162*)hi;
    __nv_bfloat162* l2 = (__nv_bfloat162*)lo;
    for (; i < n4; i += stride) {
        float4 v = s4[i];
        __nv_bfloat16 hx = __float2bfloat16(v.x), hy = __float2bfloat16(v.y);
        __nv_bfloat16 hz = __float2bfloat16(v.z), hw = __float2bfloat16(v.w);
        __nv_bfloat16 lx = __float2bfloat16(v.x - __bfloat162float(hx));
        __nv_bfloat16 ly = __float2bfloat16(v.y - __bfloat162float(hy));
        __nv_bfloat16 lz = __float2bfloat16(v.z - __bfloat162float(hz));
        __nv_bfloat16 lw = __float2bfloat16(v.w - __bfloat162float(hw));
        __nv_bfloat162 a; a.x = hx; a.y = hy;
        __nv_bfloat162 b; b.x = hz; b.y = hw;
        __nv_bfloat162 c; c.x = lx; c.y = ly;
        __nv_bfloat162 d; d.x = lz; d.y = lw;
        h2[2 * i] = a; h2[2 * i + 1] = b;
        l2[2 * i] = c; l2[2 * i + 1] = d;
    }
}

// -------------------- tensor-core GEMM: C = (Ah+Al)@(Wh+Wl) + bias --------------------
// 128x128 CTA tile, 8 warps (4 M x 2 N), warp tile 32x64, m16n8k16 bf16 mma.
// Split product: Ah@Wh + Al@Wh + Ah@Wl (Al@Wl dropped, ~2^-18 relative).
__global__ void __launch_bounds__(256, 2)
mma_gemm_kernel(const __nv_bfloat16* __restrict__ Ahg0, const __nv_bfloat16* __restrict__ Alg0,
                const __nv_bfloat16* __restrict__ Whg0, const __nv_bfloat16* __restrict__ Wlg0,
                const float* __restrict__ bias, float* __restrict__ C)
{
    if (blockIdx.x == 0 && blockIdx.y == 0 && threadIdx.x == 0) g_bar = 0u;

    __shared__ __nv_bfloat16 Ah_s[2][128 * AS_STRIDE];
    __shared__ __nv_bfloat16 Al_s[2][128 * AS_STRIDE];
    __shared__ __nv_bfloat16 Wh_s[2][16 * WS_STRIDE];
    __shared__ __nv_bfloat16 Wl_s[2][16 * WS_STRIDE];

    const int tid  = threadIdx.x;
    const int bn   = blockIdx.x;
    const int bm   = blockIdx.y;
    const int wid  = tid >> 5;
    const int lane = tid & 31;
    const int wr   = wid & 3;      // warp row (M)
    const int wc   = wid >> 2;     // warp col (N)

    // cp.async mapping: A tiles 128x16 (thread -> row, 8-elem half); W tiles 16x128
    const int arow  = tid >> 1, ahalf = (tid & 1) * 8;
    const int wrow  = tid >> 4, wseg  = (tid & 15) * 8;

    const __nv_bfloat16* Ahg = Ahg0 + (size_t)(bm * 128 + arow) * HH + ahalf;
    const __nv_bfloat16* Alg = Alg0 + (size_t)(bm * 128 + arow) * HH + ahalf;
    const __nv_bfloat16* Whg = Whg0 + (size_t)wrow * HH + bn * 128 + wseg;
    const __nv_bfloat16* Wlg = Wlg0 + (size_t)wrow * HH + bn * 128 + wseg;

    const uint32_t bAh = smem_u32(Ah_s), bAl = smem_u32(Al_s);
    const uint32_t bWh = smem_u32(Wh_s), bWl = smem_u32(Wl_s);
    const uint32_t dA = (arow * AS_STRIDE + ahalf) * 2;
    const uint32_t dW = (wrow * WS_STRIDE + wseg) * 2;
    const uint32_t ASZ = 128 * AS_STRIDE * 2;   // bytes per A stage
    const uint32_t WSZ = 16 * WS_STRIDE * 2;    // bytes per W stage

    // ldmatrix lane address offsets
    const uint32_t aOff = (((wr * 32) + (lane & 15)) * AS_STRIDE + ((lane >> 4) << 3)) * 2;
    const uint32_t bOff = ((lane & 15) * WS_STRIDE + wc * 64 + ((lane >> 4) << 3)) * 2;

    float acc[2][8][4];
#pragma unroll
    for (int mi = 0; mi < 2; mi++)
#pragma unroll
        for (int ni = 0; ni < 8; ni++)
#pragma unroll
            for (int q = 0; q < 4; q++) acc[mi][ni][q] = 0.0f;

    // prologue: stage 0
    cp_async16(bAh + dA, Ahg);
    cp_async16(bAl + dA, Alg);
    cp_async16(bWh + dW, Whg);
    cp_async16(bWl + dW, Wlg);
    CP_COMMIT();

    for (int ks = 0; ks < 64; ks++) {
        const uint32_t cur = (ks & 1);
        if (ks < 63) {
            const uint32_t nxt = cur ^ 1;
            const int kb = (ks + 1) * 16;
            cp_async16(bAh + nxt * ASZ + dA, Ahg + kb);
            cp_async16(bAl + nxt * ASZ + dA, Alg + kb);
            cp_async16(bWh + nxt * WSZ + dW, Whg + (size_t)kb * HH);
            cp_async16(bWl + nxt * WSZ + dW, Wlg + (size_t)kb * HH);
            CP_COMMIT();
            CP_WAIT(1);
        } else {
            CP_WAIT(0);
        }
        __syncthreads();

        uint32_t ah[2][4], al[2][4];
#pragma unroll
        for (int mi = 0; mi < 2; mi++) {
            const uint32_t mofs = mi * 16 * AS_STRIDE * 2;
            ldsm_x4(ah[mi][0], ah[mi][1], ah[mi][2], ah[mi][3], bAh + cur * ASZ + aOff + mofs);
            ldsm_x4(al[mi][0], al[mi][1], al[mi][2], al[mi][3], bAl + cur * ASZ + aOff + mofs);
        }
#pragma unroll
        for (int ng = 0; ng < 4; ng++) {
            uint32_t bh[4], bl[4];
            ldsm_x4_t(bh[0], bh[1], bh[2], bh[3], bWh + cur * WSZ + bOff + ng * 32);
            ldsm_x4_t(bl[0], bl[1], bl[2], bl[3], bWl + cur * WSZ + bOff + ng * 32);
#pragma unroll
            for (int mi = 0; mi < 2; mi++) {
                mma16816(acc[mi][2 * ng],     ah[mi][0], ah[mi][1], ah[mi][2], ah[mi][3], bh[0], bh[1]);
                mma16816(acc[mi][2 * ng],     al[mi][0], al[mi][1], al[mi][2], al[mi][3], bh[0], bh[1]);
                mma16816(acc[mi][2 * ng],     ah[mi][0], ah[mi][1], ah[mi][2], ah[mi][3], bl[0], bl[1]);
                mma16816(acc[mi][2 * ng + 1], ah[mi][0], ah[mi][1], ah[mi][2], ah[mi][3], bh[2], bh[3]);
                mma16816(acc[mi][2 * ng + 1], al[mi][0], al[mi][1], al[mi][2], al[mi][3], bh[2], bh[3]);
                mma16816(acc[mi][2 * ng + 1], ah[mi][0], ah[mi][1], ah[mi][2], ah[mi][3], bl[2], bl[3]);
            }
        }
        __syncthreads();
    }

    // epilogue: add bias, store fp32
    const int gr  = lane >> 2;
    const int gc2 = (lane & 3) * 2;
#pragma unroll
    for (int mi = 0; mi < 2; mi++) {
        const int row0 = bm * 128 + wr * 32 + mi * 16 + gr;
#pragma unroll
        for (int ni = 0; ni < 8; ni++) {
            const int col = bn * 128 + wc * 64 + ni * 8 + gc2;
            const float b0 = bias[col], b1 = bias[col + 1];
            float2 v0 = { acc[mi][ni][0] + b0, acc[mi][ni][1] + b1 };
            float2 v1 = { acc[mi][ni][2] + b0, acc[mi][ni][3] + b1 };
            *(float2*)(C + (size_t)row0 * HH + col)        = v0;
            *(float2*)(C + (size_t)(row0 + 8) * HH + col)  = v1;
        }
    }
}

// -------------------- grid barrier --------------------
__device__ __forceinline__ void grid_bar_sync(unsigned target)
{
    __syncthreads();
    if (threadIdx.x == 0) {
        red_release_add(&g_bar, 1u);
        while (ld_acquire(&g_bar) < target) { }
    }
    __syncthreads();
}

// -------------------- Recurrence (fp32, pipelined h copy) --------------------
__global__ void __launch_bounds__(256, 1)
rnn_layer_kernel(float* __restrict__ xp, const float* __restrict__ Wh)
{
    extern __shared__ float sm[];
    float* w_s = sm;                         // [HH][CPC]
    float* h_s = sm + HH * CPC;              // [HH][BB]
    float* p_s = sm + HH * CPC + HH * BB;    // [8][CPC][BB]

    const int tid  = threadIdx.x;
    const int w    = tid >> 5;
    const int lane = tid & 31;
    const int c0   = blockIdx.x * CPC;

    for (int i = tid; i < HH * 2; i += 256) {
        int k = i >> 1, half = (i & 1) * 4;
        *(float4*)(w_s + k * CPC + half) = *(const float4*)(Wh + k * HH + c0 + half);
    }
    g_hA[blockIdx.x * 256 + tid] = 0.0f;

    unsigned bar = 1;
    grid_bar_sync(bar * NCTA); bar++;

    const int kbase = w * KPW;
    const uint32_t hsm = smem_u32(h_s) + kbase * BB * 4;
    const int oc = c0 + w;
    const int ob = lane;

    float* hcur = g_hA;
    float* hnxt = g_hB;

    const float*  hp = h_s + kbase * BB + lane;
    const float4* wp = (const float4*)(w_s + kbase * CPC);

    for (int t = 0; t < TT; t++) {
        const int xidx = (ob * TT + t) * HH + oc;
        const float xv = xp[xidx];

        // issue all 4 copy chunks (4KB each) as separate commit groups
        const float* src = hcur + kbase * BB;
#pragma unroll
        for (int g = 0; g < 4; g++) {
#pragma unroll
            for (int j = 0; j < 8; j++) {
                const int f4 = g * 256 + j * 32 + lane;
                cp_async16(hsm + f4 * 16, src + f4 * 4);
            }
            CP_COMMIT();
        }

        float a0 = 0.f, a1 = 0.f, a2 = 0.f, a3 = 0.f;
        float a4 = 0.f, a5 = 0.f, a6 = 0.f, a7 = 0.f;

#define RNN_CHUNK(G)                                          \
        _Pragma("unroll 4")                                   \
        for (int k = (G)*32; k < (G)*32 + 32; k++) {          \
            float  hv = hp[k * BB];                           \
            float4 wa = wp[k * 2];                            \
            float4 wb = wp[k * 2 + 1];                        \
            a0 = fmaf(hv, wa.x, a0);                          \
            a1 = fmaf(hv, wa.y, a1);                          \
            a2 = fmaf(hv, wa.z, a2);                          \
            a3 = fmaf(hv, wa.w, a3);                          \
            a4 = fmaf(hv, wb.x, a4);                          \
            a5 = fmaf(hv, wb.y, a5);                          \
            a6 = fmaf(hv, wb.z, a6);                          \
            a7 = fmaf(hv, wb.w, a7);                          \
        }

        CP_WAIT(3); __syncwarp(); RNN_CHUNK(0);
        CP_WAIT(2); __syncwarp(); RNN_CHUNK(1);
        CP_WAIT(1); __syncwarp(); RNN_CHUNK(2);
        CP_WAIT(0); __syncwarp(); RNN_CHUNK(3);
#undef RNN_CHUNK

        float* pw = p_s + w * (CPC * BB) + lane;
        pw[0 * BB] = a0; pw[1 * BB] = a1; pw[2 * BB] = a2; pw[3 * BB] = a3;
        pw[4 * BB] = a4; pw[5 * BB] = a5; pw[6 * BB] = a6; pw[7 * BB] = a7;
        __syncthreads();

        const float* pr = p_s + w * BB + lane;
        float s = pr[0];
#pragma unroll
        for (int j = 1; j < 8; j++) s += pr[j * (CPC * BB)];

        const float hn = tanh_acc(xv + s);
        xp[xidx] = hn;
        hnxt[oc * BB + ob] = hn;

        grid_bar_sync(bar * NCTA); bar++;
        float* tmp = hcur; hcur = hnxt; hnxt = tmp;
    }
}

// -------------------- Final dense head --------------------
__global__ void __launch_bounds__(256)
fc_kernel(const float* __restrict__ seq, const float* __restrict__ fcW,
          const float* __restrict__ fcb, float* __restrict__ out)
{
    const int o  = blockIdx.x * 256 + threadIdx.x;
    const int bq = blockIdx.y;
    const float* h = seq + (bq * TT + (TT - 1)) * HH;
    float acc = fcb[o];
#pragma unroll 8
    for (int k = 0; k < HH; k++)
        acc = fmaf(h[k], fcW[k * HH + o], acc);
    out[bq * HH + o] = acc;
}

// -------------------- launch --------------------
extern "C" void kernel_launch(void* const* d_in, const int* in_sizes, int n_in,
                              void* d_out, int out_size)
{
    const float* x   = (const float*)d_in[0];
    const float* Wi  = (const float*)d_in[1];
    const float* Wh  = (const float*)d_in[2];
    const float* bl  = (const float*)d_in[3];
    const float* fcW = (const float*)d_in[4];
    const float* fcb = (const float*)d_in[5];
    float* out = (float*)d_out;

    cudaFuncSetAttribute(rnn_layer_kernel,
                         cudaFuncAttributeMaxDynamicSharedMemorySize, RNN_SMEM);

    float *S;
    __nv_bfloat16 *Ah, *Al, *Wih, *Wil;
    cudaGetSymbolAddress((void**)&S,   g_S);
    cudaGetSymbolAddress((void**)&Ah,  g_Ah);
    cudaGetSymbolAddress((void**)&Al,  g_Al);
    cudaGetSymbolAddress((void**)&Wih, g_Wih);
    cudaGetSymbolAddress((void**)&Wil, g_Wil);

    const dim3 ggrid(8, 256);
    const int NSEQ4 = BB * TT * HH / 4;
    const int NW4   = LL * HH * HH / 4;

    // convert inputs and all Wi layers to bf16 hi/lo
    split_kernel<<<4096, 256>>>(x,  Ah, Al, NSEQ4);
    split_kernel<<<2048, 256>>>(Wi, Wih, Wil, NW4);

    for (int l = 0; l < LL; l++) {
        mma_gemm_kernel<<<ggrid, 256>>>(Ah, Al,
                                        Wih + (size_t)l * HH * HH,
                                        Wil + (size_t)l * HH * HH,
                                        bl + l * HH, S);
        rnn_layer_kernel<<<NCTA, 256, RNN_SMEM>>>(S, Wh + (size_t)l * HH * HH);
        if (l < LL - 1)
            split_kernel<<<4096, 256>>>(S, Ah, Al, NSEQ4);
    }

    fc_kernel<<<dim3(HH / 256, BB), 256>>>(S, fcW, fcb, out);
}